// round 17
// baseline (speedup 1.0000x reference)
#include <cuda_runtime.h>
#include <cuda_fp16.h>
#include <cstdint>

#define S_LEN 2048
#define HD    512        // H_NUM * D_DIM
#define H_NUM 8
#define QT    128        // queries per block
#define KR    256        // key rows cached per block (QT + 2*64)
#define STR   144        // smem row stride in BYTES (72 fp16): conflict-free ldmatrix

#define OFF_Q 0
#define OFF_K (128 * STR)              // 18432
#define OFF_V (OFF_K + KR * STR)       // 55296
#define SMEM_BYTES (OFF_V + KR * STR)  // 92160

__device__ __forceinline__ uint32_t smem_u32(const void* p) {
    uint32_t a;
    asm("{ .reg .u64 t; cvta.to.shared.u64 t, %1; cvt.u32.u64 %0, t; }" : "=r"(a) : "l"(p));
    return a;
}
__device__ __forceinline__ void ldsm4(uint32_t* r, uint32_t a) {
    asm volatile("ldmatrix.sync.aligned.m8n8.x4.shared.b16 {%0,%1,%2,%3}, [%4];"
                 : "=r"(r[0]), "=r"(r[1]), "=r"(r[2]), "=r"(r[3]) : "r"(a));
}
__device__ __forceinline__ void ldsm4t(uint32_t* r, uint32_t a) {
    asm volatile("ldmatrix.sync.aligned.m8n8.x4.trans.shared.b16 {%0,%1,%2,%3}, [%4];"
                 : "=r"(r[0]), "=r"(r[1]), "=r"(r[2]), "=r"(r[3]) : "r"(a));
}
// non-volatile: pure register op, lets ptxas schedule freely
__device__ __forceinline__ void mma_f16(float* c, const uint32_t* a, uint32_t b0, uint32_t b1) {
    asm("mma.sync.aligned.m16n8k16.row.col.f32.f16.f16.f32 "
        "{%0,%1,%2,%3},{%4,%5,%6,%7},{%8,%9},{%0,%1,%2,%3};"
        : "+f"(c[0]), "+f"(c[1]), "+f"(c[2]), "+f"(c[3])
        : "r"(a[0]), "r"(a[1]), "r"(a[2]), "r"(a[3]), "r"(b0), "r"(b1));
}
__device__ __forceinline__ uint32_t pack_h2(float a, float b) {
    __half2 t = __floats2half2_rn(a, b);
    return *reinterpret_cast<uint32_t*>(&t);
}
__device__ __forceinline__ float round_h(float x) {
    return __half2float(__float2half_rn(x));
}

__global__ __launch_bounds__(256, 1)
void mca_swa_f16_kernel(const float* __restrict__ Q,
                        const float* __restrict__ K,
                        const float* __restrict__ V,
                        float* __restrict__ O)
{
    extern __shared__ unsigned char sm[];
    const uint32_t sbase = smem_u32(sm);
    const int tid = threadIdx.x;
    const int q0  = blockIdx.x * QT;
    const int h   = blockIdx.y;

    // ---------- prologue: Q (128 rows) + K/V window rows [q0-64, q0+192) ----------
    #pragma unroll
    for (int i = 0; i < 8; i++) {
        int idx = tid + 256 * i;          // 0..2047 float4
        int row = idx >> 4;
        int d0  = (idx & 15) * 4;
        float4 t = *reinterpret_cast<const float4*>(Q + ((size_t)(q0 + row) * H_NUM + h) * 64 + d0);
        t.x *= 0.125f; t.y *= 0.125f; t.z *= 0.125f; t.w *= 0.125f;
        *reinterpret_cast<uint2*>(sm + OFF_Q + row * STR + d0 * 2) =
            make_uint2(pack_h2(t.x, t.y), pack_h2(t.z, t.w));
    }
    #pragma unroll
    for (int i = 0; i < 16; i++) {
        int idx = tid + 256 * i;          // 0..4095 float4 -> rows [0,256)
        int row = idx >> 4;
        int d0  = (idx & 15) * 4;
        int key = q0 - 64 + row;
        float4 tk = make_float4(0.f, 0.f, 0.f, 0.f);
        float4 tv = make_float4(0.f, 0.f, 0.f, 0.f);
        if ((unsigned)key < (unsigned)S_LEN) {
            size_t base = ((size_t)key * H_NUM + h) * 64 + d0;
            tk = *reinterpret_cast<const float4*>(K + base);
            tv = *reinterpret_cast<const float4*>(V + base);
        }
        int off = row * STR + d0 * 2;
        *reinterpret_cast<uint2*>(sm + OFF_K + off) =
            make_uint2(pack_h2(tk.x, tk.y), pack_h2(tk.z, tk.w));
        *reinterpret_cast<uint2*>(sm + OFF_V + off) =
            make_uint2(pack_h2(tv.x, tv.y), pack_h2(tv.z, tv.w));
    }
    __syncthreads();

    const int l    = tid & 31;
    const int w    = tid >> 5;
    const int half = w >> 2;              // split-K half
    const int p    = w & 3;               // query-tile id (0..3), 32 queries each
    const int qr0  = p * 32;

    const uint32_t aOff = (uint32_t)((qr0 + (l & 15)) * STR + (8 * (l >> 4)) * 2);               // A (Q), tile0
    const uint32_t bOff = (uint32_t)(((l & 7) + 8 * (l >> 4)) * STR + (8 * ((l >> 3) & 1)) * 2); // B (K)
    const uint32_t vOff = (uint32_t)(((l & 7) + 8 * ((l >> 3) & 1)) * STR + (8 * (l >> 4)) * 2); // B (V, trans)

    // hoist Q A-fragments for both m16 tiles (group-invariant)
    uint32_t qh0[4][4], qh1[4][4];
    #pragma unroll
    for (int kk = 0; kk < 4; kk++) {
        ldsm4(qh0[kk], sbase + OFF_Q + aOff + kk * 32);
        ldsm4(qh1[kk], sbase + OFF_Q + aOff + 16 * STR + kk * 32);
    }

    float oacc0[32], oacc1[32];
    #pragma unroll
    for (int i = 0; i < 32; i++) { oacc0[i] = 0.f; oacc1[i] = 0.f; }
    float rs[4] = {0.f, 0.f, 0.f, 0.f};   // tile0: rs[0],rs[1]; tile1: rs[2],rs[3]
    const int mrow0 = qr0 + (l >> 2);

    auto do_group = [&](int g) {
        const uint32_t kbase = sbase + (uint32_t)((qr0 + g * 16) * STR);

        // QK for both tiles: K fragment shared
        float s0[8], s1[8];
        #pragma unroll
        for (int i = 0; i < 8; i++) { s0[i] = 0.f; s1[i] = 0.f; }
        #pragma unroll
        for (int kk = 0; kk < 4; kk++) {
            uint32_t kh_[4];
            ldsm4(kh_, kbase + OFF_K + bOff + kk * 32);
            mma_f16(&s0[0], qh0[kk], kh_[0], kh_[1]);
            mma_f16(&s0[4], qh0[kk], kh_[2], kh_[3]);
            mma_f16(&s1[0], qh1[kk], kh_[0], kh_[1]);
            mma_f16(&s1[4], qh1[kk], kh_[2], kh_[3]);
        }

        // hoist V fragments: latency hides under the exp chains
        uint32_t vh_[4][4];
        #pragma unroll
        for (int dg = 0; dg < 4; dg++)
            ldsm4t(vh_[dg], kbase + OFF_V + vOff + dg * 32);

        // mask + exp per tile; round P to fp16 (rowsum uses SAME rounded values)
        const int krow0 = q0 - 64 + qr0 + g * 16;
        const bool kok = (krow0 >= 0) && (krow0 + 16 <= S_LEN);

        // tile0 (rows qr0..qr0+15): interior g in [1,7]
        if (kok && g >= 1 && g <= 7) {
            #pragma unroll
            for (int i = 0; i < 8; i++) s0[i] = round_h(__expf(s0[i]));
            rs[0] += s0[0] + s0[1] + s0[4] + s0[5];
            rs[1] += s0[2] + s0[3] + s0[6] + s0[7];
        } else {
            #pragma unroll
            for (int t = 0; t < 2; t++) {
                const int cb = qr0 + g * 16 + t * 8 + 2 * (l & 3);
                #pragma unroll
                for (int e = 0; e < 4; e++) {
                    int m = mrow0 + ((e >> 1) << 3);
                    int c = cb + (e & 1);
                    int key = q0 - 64 + c;
                    bool v = ((unsigned)(c - m) <= 128u) && ((unsigned)key < (unsigned)S_LEN);
                    float pp = v ? round_h(__expf(s0[t * 4 + e])) : 0.f;
                    s0[t * 4 + e] = pp;
                    rs[(e >> 1)] += pp;
                }
            }
        }
        // tile1 (rows qr0+16..qr0+31): interior g in [2,8]
        if (kok && g >= 2 && g <= 8) {
            #pragma unroll
            for (int i = 0; i < 8; i++) s1[i] = round_h(__expf(s1[i]));
            rs[2] += s1[0] + s1[1] + s1[4] + s1[5];
            rs[3] += s1[2] + s1[3] + s1[6] + s1[7];
        } else {
            #pragma unroll
            for (int t = 0; t < 2; t++) {
                const int cb = qr0 + g * 16 + t * 8 + 2 * (l & 3);
                #pragma unroll
                for (int e = 0; e < 4; e++) {
                    int m = mrow0 + 16 + ((e >> 1) << 3);
                    int c = cb + (e & 1);
                    int key = q0 - 64 + c;
                    bool v = ((unsigned)(c - m) <= 128u) && ((unsigned)key < (unsigned)S_LEN);
                    float pp = v ? round_h(__expf(s1[t * 4 + e])) : 0.f;
                    s1[t * 4 + e] = pp;
                    rs[2 + (e >> 1)] += pp;
                }
            }
        }

        // PV for both tiles: V fragment shared
        uint32_t pa0[4], pa1[4];
        pa0[0] = pack_h2(s0[0], s0[1]); pa0[1] = pack_h2(s0[2], s0[3]);
        pa0[2] = pack_h2(s0[4], s0[5]); pa0[3] = pack_h2(s0[6], s0[7]);
        pa1[0] = pack_h2(s1[0], s1[1]); pa1[1] = pack_h2(s1[2], s1[3]);
        pa1[2] = pack_h2(s1[4], s1[5]); pa1[3] = pack_h2(s1[6], s1[7]);
        #pragma unroll
        for (int dg = 0; dg < 4; dg++) {
            mma_f16(&oacc0[dg * 8],     pa0, vh_[dg][0], vh_[dg][1]);
            mma_f16(&oacc0[dg * 8 + 4], pa0, vh_[dg][2], vh_[dg][3]);
            mma_f16(&oacc1[dg * 8],     pa1, vh_[dg][0], vh_[dg][1]);
            mma_f16(&oacc1[dg * 8 + 4], pa1, vh_[dg][2], vh_[dg][3]);
        }
    };

    // Band: rows [qr0, qr0+160) = 10 groups of 16; balanced split-K 5/5.
    if (half == 0) { do_group(0); do_group(2); do_group(4); do_group(6); do_group(8); }
    else           { do_group(1); do_group(3); do_group(5); do_group(7); do_group(9); }

    // ---- pairwise split-K reduction through (dead) Q/K smem region ----
    __syncthreads();
    float* red = reinterpret_cast<float*>(sm) + (size_t)(p * 32 + l) * 68;
    if (half == 1) {
        #pragma unroll
        for (int i = 0; i < 32; i++) red[i] = oacc0[i];
        #pragma unroll
        for (int i = 0; i < 32; i++) red[32 + i] = oacc1[i];
        red[64] = rs[0]; red[65] = rs[1]; red[66] = rs[2]; red[67] = rs[3];
    }
    __syncthreads();
    if (half == 0) {
        #pragma unroll
        for (int i = 0; i < 32; i++) oacc0[i] += red[i];
        #pragma unroll
        for (int i = 0; i < 32; i++) oacc1[i] += red[32 + i];
        rs[0] += red[64]; rs[1] += red[65]; rs[2] += red[66]; rs[3] += red[67];

        #pragma unroll
        for (int r = 0; r < 4; r++) {
            rs[r] += __shfl_xor_sync(0xffffffffu, rs[r], 1);
            rs[r] += __shfl_xor_sync(0xffffffffu, rs[r], 2);
        }
        const float i0 = 1.0f / rs[0];
        const float i1 = 1.0f / rs[1];
        const float i2 = 1.0f / rs[2];
        const float i3 = 1.0f / rs[3];

        const int mg = q0 + qr0 + (l >> 2);
        #pragma unroll
        for (int fr = 0; fr < 8; fr++) {
            int col = fr * 8 + 2 * (l & 3);
            float2 r0, r1, r2, r3;
            r0.x = oacc0[fr * 4 + 0] * i0; r0.y = oacc0[fr * 4 + 1] * i0;
            r1.x = oacc0[fr * 4 + 2] * i1; r1.y = oacc0[fr * 4 + 3] * i1;
            r2.x = oacc1[fr * 4 + 0] * i2; r2.y = oacc1[fr * 4 + 1] * i2;
            r3.x = oacc1[fr * 4 + 2] * i3; r3.y = oacc1[fr * 4 + 3] * i3;
            *reinterpret_cast<float2*>(O + (size_t)mg * HD + h * 64 + col) = r0;
            *reinterpret_cast<float2*>(O + (size_t)(mg + 8) * HD + h * 64 + col) = r1;
            *reinterpret_cast<float2*>(O + (size_t)(mg + 16) * HD + h * 64 + col) = r2;
            *reinterpret_cast<float2*>(O + (size_t)(mg + 24) * HD + h * 64 + col) = r3;
        }
    }
}

extern "C" void kernel_launch(void* const* d_in, const int* in_sizes, int n_in,
                              void* d_out, int out_size)
{
    const float* q = (const float*)d_in[0];
    const float* k = (const float*)d_in[1];
    const float* v = (const float*)d_in[2];
    float* out = (float*)d_out;

    cudaFuncSetAttribute(mca_swa_f16_kernel,
                         cudaFuncAttributeMaxDynamicSharedMemorySize, SMEM_BYTES);

    dim3 grid(S_LEN / QT, H_NUM);
    mca_swa_f16_kernel<<<grid, 256, SMEM_BYTES>>>(q, k, v, out);
}